// round 5
// baseline (speedup 1.0000x reference)
#include <cuda_runtime.h>
#include <math.h>

// ---------------- problem constants ----------------
#define NB   64        // batch
#define NN_  200       // nodes
#define NU   64        // rnn units
#define NL   4         // layers
#define NT   12        // input_len == output_len
#define F0   264       // layer-0 features (200 + 64)
#define F1   128       // layer>0 features (64 + 64)
#define BF0  (F0*NB)   // 16896
#define BF1  (F1*NB)   // 8192
#define SEG0 (NN_*BF0) // 3,379,200
#define NNSQ 40000     // N*N
#define HSZ  (NN_*NU*NB)   // 819200, hidden layout [n][u][b]

typedef unsigned long long ull;

// ---------------- scratch (device globals; no allocation allowed) ----------
__device__ float g_X[3*SEG0];          // [X0 ; X1 ; X2], rows=node, cols=f*64+b
__device__ float g_SS[400*200];        // [S ; 2S^2 - I]
__device__ float g_h[NL][HSZ];         // hidden per layer, [n][u][b]
__device__ float g_gates[NN_*128*NB];  // gates [n][o][b], o in [0,128)
__device__ float g_W[746496];          // reordered weights [k][f][o] per (side,layer,g/c)

// ---------------- f32x2 helpers ----------------
__device__ __forceinline__ ull pack2(float lo, float hi) {
    ull r; asm("mov.b64 %0,{%1,%2};" : "=l"(r) : "f"(lo), "f"(hi)); return r;
}
__device__ __forceinline__ ull ffma2(ull a, ull b, ull c) {
    ull d; asm("fma.rn.f32x2 %0,%1,%2,%3;" : "=l"(d) : "l"(a), "l"(b), "l"(c)); return d;
}
__device__ __forceinline__ float2 upk(ull v) {
    float2 f; asm("mov.b64 {%0,%1},%2;" : "=f"(f.x), "=f"(f.y) : "l"(v)); return f;
}

// ---------------- setup kernels ----------------
// SS[0:200] = S ; SS[200:400] = 2*S@S - I
__global__ void build_SS(const float* __restrict__ S) {
    int m = blockIdx.x;
    int k = threadIdx.x;
    if (k >= 200) return;
    if (m < 200) { g_SS[m*200 + k] = S[m*200 + k]; return; }
    int r = m - 200;
    float acc = 0.f;
    for (int j = 0; j < 200; j++) acc += S[r*200 + j] * S[j*200 + k];
    g_SS[m*200 + k] = 2.f*acc - (r == k ? 1.f : 0.f);
}

// src rows are (f*3+k); dst is [k][f][o] contiguous
__global__ void reorder_W(const float* __restrict__ src, int dstOff, int F, int O) {
    int idx = blockIdx.x * blockDim.x + threadIdx.x;
    int tot = 3 * F * O;
    if (idx >= tot) return;
    int k   = idx / (F * O);
    int rem = idx - k * F * O;
    int f   = rem / O;
    int o   = rem - f * O;
    g_W[dstOff + idx] = src[(f*3 + k)*O + o];
}

__global__ void zero_h() {
    int idx = blockIdx.x * blockDim.x + threadIdx.x;
    if (idx < NL*HSZ) ((float*)g_h)[idx] = 0.f;
}

// ---------------- pack kernels ----------------
// layer-0 input features (f<200) from src[b*strideB + n*200 + f] -> g_X[n][f][b]
// src == nullptr -> zeros (decoder go)
__global__ void pack_l0_input(const float* __restrict__ src, int strideB) {
    __shared__ float s[32][33];
    int n  = blockIdx.x;
    int f0 = blockIdx.y * 32;
    int b0 = blockIdx.z * 32;
    int tx = threadIdx.x, ty = threadIdx.y;     // 32 x 8
    if (src) {
        #pragma unroll
        for (int i = 0; i < 4; i++) {
            int b = b0 + ty + 8*i;
            int f = f0 + tx;
            s[ty + 8*i][tx] = (f < 200) ? src[b*strideB + n*200 + f] : 0.f;
        }
    } else {
        #pragma unroll
        for (int i = 0; i < 4; i++) s[ty + 8*i][tx] = 0.f;
    }
    __syncthreads();
    #pragma unroll
    for (int i = 0; i < 4; i++) {
        int f = f0 + ty + 8*i;
        if (f < 200) g_X[n*BF0 + f*64 + b0 + tx] = s[tx][ty + 8*i];
    }
}

// copy h[srcLayer] ([n][u][b]) into X0 at feature offset dstF (pure coalesced copy)
__global__ void pack_h_block(int srcLayer, int dstF, int BFl) {
    int idx = blockIdx.x * blockDim.x + threadIdx.x;
    if (idx >= HSZ) return;
    int n   = idx >> 12;
    int rem = idx & 4095;
    g_X[n*BFl + dstF*64 + rem] = g_h[srcLayer][idx];
}

// X0 state columns = r * h  (r = gates[:, 0:64])
__global__ void pack_rstate(int layer, int inDim, int BFl) {
    int idx = blockIdx.x * blockDim.x + threadIdx.x;
    if (idx >= HSZ) return;
    int n   = idx >> 12;
    int rem = idx & 4095;
    g_X[n*BFl + inDim*64 + rem] = g_gates[n*8192 + rem] * g_h[layer][idx];
}

// ---------------- GEMM 1: Y(400 x cols) = SS(400x200) @ X0(200 x cols) ----------
// cols indexed f*64+b with row stride BFl; output written at g_X + SEGl (X1/X2)
__global__ __launch_bounds__(256) void gemm_support(int BFl, int SEGl, int colOff) {
    __shared__ float As[8][64];
    __shared__ float Bs[8][128];
    const int m0 = blockIdx.y * 64;
    const int n0 = colOff + blockIdx.x * 128;
    const int t  = threadIdx.x;
    const int tr = t >> 4, tc = t & 15;
    ull acc[4][4];
    #pragma unroll
    for (int i = 0; i < 4; i++)
        #pragma unroll
        for (int j = 0; j < 4; j++) acc[i][j] = 0ull;

    const int ar = t >> 2;          // 0..63 (rows of A tile)
    const int ac = (t & 3) * 2;     // 0,2,4,6 (col pair)
    const int br = t >> 5;          // 0..7
    const int bc = (t & 31) * 4;    // float4 column

    for (int k0 = 0; k0 < 200; k0 += 8) {
        float2 av = make_float2(0.f, 0.f);
        if (m0 + ar < 400) av = *(const float2*)&g_SS[(m0 + ar)*200 + k0 + ac];
        As[ac][ar] = av.x; As[ac + 1][ar] = av.y;
        *(float4*)&Bs[br][bc] = *(const float4*)&g_X[(k0 + br)*BFl + n0 + bc];
        __syncthreads();
        #pragma unroll
        for (int kk = 0; kk < 8; kk++) {
            ull ap[4], bp[4];
            #pragma unroll
            for (int i = 0; i < 4; i++) { float a = As[kk][tr*4 + i]; ap[i] = pack2(a, a); }
            #pragma unroll
            for (int j = 0; j < 4; j++) bp[j] = *(const ull*)&Bs[kk][tc*2 + 32*j];
            #pragma unroll
            for (int i = 0; i < 4; i++)
                #pragma unroll
                for (int j = 0; j < 4; j++) acc[i][j] = ffma2(ap[i], bp[j], acc[i][j]);
        }
        __syncthreads();
    }
    float* C = g_X + SEGl;
    #pragma unroll
    for (int i = 0; i < 4; i++) {
        int m = m0 + tr*4 + i;
        if (m < 400) {
            #pragma unroll
            for (int j = 0; j < 4; j++)
                *(ull*)&C[m*BFl + n0 + tc*2 + 32*j] = acc[i][j];
        }
    }
}

// ---------------- GEMM 2: combine X0/X1/X2 with reordered weights + epilogue ----
// rows of the GEMM are (n,b): one block handles one node n (64 batch rows).
// MODE 0: sigmoid -> g_gates  (O=128) ; MODE 1: tanh + GRU update of g_h[layer] (O=64)
template <int MODE>
__global__ __launch_bounds__(256) void gemm_combine(int F, int wOff,
                                                    const float* __restrict__ bias,
                                                    int layer, int O) {
    __shared__ float As[8][64];
    __shared__ float Ws[8][64];
    const int BFl  = F * 64;
    const int SEGl = 200 * BFl;
    const int n  = blockIdx.y;
    const int o0 = blockIdx.x * 64;
    const int t  = threadIdx.x;
    const int tr = t >> 4, tc = t & 15;
    ull acc[4][2];
    #pragma unroll
    for (int i = 0; i < 4; i++) { acc[i][0] = 0ull; acc[i][1] = 0ull; }

    const int ar = t & 63, ac = t >> 6;       // A tile: contiguous in r
    const int wr = t >> 5, wc = (t & 31) * 2; // W tile: float2 per thread

    for (int ks = 0; ks < 3; ks++) {
        const float* Aseg = g_X + ks*SEGl + n*BFl;
        const float* Wseg = g_W + wOff + ks*F*O;
        for (int k0 = 0; k0 < F; k0 += 8) {
            As[ac][ar]     = Aseg[(k0 + ac)*64 + ar];
            As[ac + 4][ar] = Aseg[(k0 + ac + 4)*64 + ar];
            *(ull*)&Ws[wr][wc] = *(const ull*)&Wseg[(k0 + wr)*O + o0 + wc];
            __syncthreads();
            #pragma unroll
            for (int kk = 0; kk < 8; kk++) {
                ull ap[4];
                #pragma unroll
                for (int i = 0; i < 4; i++) { float a = As[kk][tr*4 + i]; ap[i] = pack2(a, a); }
                ull b0v = *(const ull*)&Ws[kk][tc*2];
                ull b1v = *(const ull*)&Ws[kk][tc*2 + 32];
                #pragma unroll
                for (int i = 0; i < 4; i++) {
                    acc[i][0] = ffma2(ap[i], b0v, acc[i][0]);
                    acc[i][1] = ffma2(ap[i], b1v, acc[i][1]);
                }
            }
            __syncthreads();
        }
    }
    #pragma unroll
    for (int i = 0; i < 4; i++) {
        int b = tr*4 + i;
        #pragma unroll
        for (int j = 0; j < 2; j++) {
            int o = o0 + tc*2 + 32*j;
            float2 v = upk(acc[i][j]);
            float v0 = v.x + bias[o];
            float v1 = v.y + bias[o + 1];
            if (MODE == 0) {
                v0 = 1.f / (1.f + expf(-v0));
                v1 = 1.f / (1.f + expf(-v1));
                g_gates[n*8192 + o*64 + b]       = v0;
                g_gates[n*8192 + (o + 1)*64 + b] = v1;
            } else {
                float c0 = tanhf(v0), c1 = tanhf(v1);
                float u0 = g_gates[n*8192 + (64 + o)*64 + b];
                float u1 = g_gates[n*8192 + (64 + o + 1)*64 + b];
                float* hp = g_h[layer];
                float h0 = hp[n*4096 + o*64 + b];
                float h1 = hp[n*4096 + (o + 1)*64 + b];
                hp[n*4096 + o*64 + b]       = u0*h0 + (1.f - u0)*c0;
                hp[n*4096 + (o + 1)*64 + b] = u1*h1 + (1.f - u1)*c1;
            }
        }
    }
}

// ---------------- projection: out_t = h3 @ proj_W + proj_b -------------------
__global__ __launch_bounds__(256) void gemm_proj(const float* __restrict__ W,
                                                 const float* __restrict__ bias,
                                                 float* __restrict__ out, int t) {
    __shared__ float As[8][64];
    __shared__ float Ws[8][64];
    const int n  = blockIdx.y;
    const int o0 = blockIdx.x * 64;
    const int tt = threadIdx.x;
    const int tr = tt >> 4, tc = tt & 15;
    ull acc[4][2];
    #pragma unroll
    for (int i = 0; i < 4; i++) { acc[i][0] = 0ull; acc[i][1] = 0ull; }

    const int ar = tt & 63, ac = tt >> 6;
    const int wr = tt >> 5, wc = (tt & 31) * 2;
    const float* A = g_h[3] + n*4096;

    for (int k0 = 0; k0 < 64; k0 += 8) {
        As[ac][ar]     = A[(k0 + ac)*64 + ar];
        As[ac + 4][ar] = A[(k0 + ac + 4)*64 + ar];
        ull wv = 0ull;
        if (o0 + wc < 200) wv = *(const ull*)&W[(k0 + wr)*200 + o0 + wc];
        *(ull*)&Ws[wr][wc] = wv;
        __syncthreads();
        #pragma unroll
        for (int kk = 0; kk < 8; kk++) {
            ull ap[4];
            #pragma unroll
            for (int i = 0; i < 4; i++) { float a = As[kk][tr*4 + i]; ap[i] = pack2(a, a); }
            ull b0v = *(const ull*)&Ws[kk][tc*2];
            ull b1v = *(const ull*)&Ws[kk][tc*2 + 32];
            #pragma unroll
            for (int i = 0; i < 4; i++) {
                acc[i][0] = ffma2(ap[i], b0v, acc[i][0]);
                acc[i][1] = ffma2(ap[i], b1v, acc[i][1]);
            }
        }
        __syncthreads();
    }
    #pragma unroll
    for (int i = 0; i < 4; i++) {
        int b = tr*4 + i;
        #pragma unroll
        for (int j = 0; j < 2; j++) {
            int o = o0 + tc*2 + 32*j;
            if (o < 200) {
                float2 v = upk(acc[i][j]);
                v.x += bias[o];
                v.y += bias[o + 1];
                *(ull*)&out[b*480000 + t*40000 + n*200 + o] = pack2(v.x, v.y);
            }
        }
    }
}

// ---------------- host driver ----------------
extern "C" void kernel_launch(void* const* d_in, const int* in_sizes, int n_in,
                              void* d_out, int out_size) {
    const float* inputs  = (const float*)d_in[0];
    const float* support = (const float*)d_in[1];
    const float* projW   = (const float*)d_in[18];
    const float* projb   = (const float*)d_in[19];
    float* out = (float*)d_out;

    const float* Wsrc[2][4][2];
    const float* Bsrc[2][4][2];
    for (int s = 0; s < 2; s++) {
        int base = (s == 0) ? 2 : 10;
        Wsrc[s][0][0] = (const float*)d_in[base + 0];
        Bsrc[s][0][0] = (const float*)d_in[base + 1];
        Wsrc[s][0][1] = (const float*)d_in[base + 2];
        Bsrc[s][0][1] = (const float*)d_in[base + 3];
        const float* Wg = (const float*)d_in[base + 4];
        const float* Bg = (const float*)d_in[base + 5];
        const float* Wc = (const float*)d_in[base + 6];
        const float* Bc = (const float*)d_in[base + 7];
        for (int l = 1; l < 4; l++) {
            Wsrc[s][l][0] = Wg + (l - 1) * 384 * 128;
            Bsrc[s][l][0] = Bg + (l - 1) * 128;
            Wsrc[s][l][1] = Wc + (l - 1) * 384 * 64;
            Bsrc[s][l][1] = Bc + (l - 1) * 64;
        }
    }
    int wOff[2][4][2];
    for (int s = 0; s < 2; s++) {
        int base = s * 373248;
        wOff[s][0][0] = base;
        wOff[s][0][1] = base + 101376;
        for (int l = 1; l < 4; l++) {
            wOff[s][l][0] = base + 152064 + (l - 1) * 73728;
            wOff[s][l][1] = wOff[s][l][0] + 49152;
        }
    }

    // setup (runs every launch — deterministic, cheap)
    build_SS<<<400, 256>>>(support);
    zero_h<<<(NL*HSZ + 255) / 256, 256>>>();
    for (int s = 0; s < 2; s++)
        for (int l = 0; l < 4; l++) {
            int F = (l == 0) ? F0 : F1;
            reorder_W<<<(3*F*128 + 255) / 256, 256>>>(Wsrc[s][l][0], wOff[s][l][0], F, 128);
            reorder_W<<<(3*F*64  + 255) / 256, 256>>>(Wsrc[s][l][1], wOff[s][l][1], F, 64);
        }

    auto cell = [&](int s, int l, const float* l0src) {
        int F     = (l == 0) ? F0 : F1;
        int BFl   = F * 64;
        int SEGl  = 200 * BFl;
        int inDim = F - 64;
        // pack input + state halves of X0 ([n][f][b])
        if (l == 0) pack_l0_input<<<dim3(200, 7, 2), dim3(32, 8)>>>(l0src, 480000);
        else        pack_h_block<<<(HSZ + 255) / 256, 256>>>(l - 1, 0, BFl);
        pack_h_block<<<(HSZ + 255) / 256, 256>>>(l, inDim, BFl);
        // X1/X2 over all columns; gates
        gemm_support<<<dim3(BFl / 128, 7), 256>>>(BFl, SEGl, 0);
        gemm_combine<0><<<dim3(2, 200), 256>>>(F, wOff[s][l][0], Bsrc[s][l][0], l, 128);
        // candidate: only state columns re-diffused (input columns of X1/X2 reused)
        pack_rstate<<<(HSZ + 255) / 256, 256>>>(l, inDim, BFl);
        gemm_support<<<dim3(32, 7), 256>>>(BFl, SEGl, inDim * 64);
        gemm_combine<1><<<dim3(1, 200), 256>>>(F, wOff[s][l][1], Bsrc[s][l][1], l, 64);
    };

    // encoder
    for (int t = 0; t < NT; t++) {
        cell(0, 0, inputs + t * NNSQ);
        for (int l = 1; l < 4; l++) cell(0, l, nullptr);
    }
    // decoder
    for (int t = 0; t < NT; t++) {
        cell(1, 0, (t == 0) ? nullptr : out + (t - 1) * NNSQ);
        for (int l = 1; l < 4; l++) cell(1, l, nullptr);
        gemm_proj<<<dim3(4, 200), 256>>>(projW, projb, out, t);
    }
    (void)in_sizes; (void)n_in; (void)out_size;
}